// round 1
// baseline (speedup 1.0000x reference)
#include <cuda_runtime.h>
#include <math.h>

#define B_SZ 32
#define T_SZ 1024
#define I_SZ 512
#define H_SZ 1024
#define DT_C 0.1f

// ------------------------------------------------------------------
// Persistent-kernel global state (allowed: __device__ globals)
// ------------------------------------------------------------------
#define RBLK 128
__device__ float g_h[2][B_SZ * H_SZ];
__device__ volatile int g_arrive[RBLK];
__device__ volatile int g_release;

__global__ void reset_kernel() {
    int idx = blockIdx.x * blockDim.x + threadIdx.x;
    if (idx < B_SZ * H_SZ) g_h[0][idx] = 0.0f;
    if (idx < RBLK) g_arrive[idx] = 0;
    if (idx == 0) g_release = 0;
}

// ------------------------------------------------------------------
// xW GEMM: C[M=B*T, H] = X[M, I] @ W[H, I]^T   (fp32)
// 128x64 block tile, BK=16, 256 threads, 8x4 micro-tile
// ------------------------------------------------------------------
#define GBM 128
#define GBN 64
#define GBK 16

__global__ void __launch_bounds__(256) gemm_xw(
    const float* __restrict__ X, const float* __restrict__ W,
    float* __restrict__ C)
{
    __shared__ float Xs[GBK][GBM];
    __shared__ float Ws[GBK][GBN + 4];
    const int tid = threadIdx.x;
    const int tx = tid & 15;   // 16 -> N
    const int ty = tid >> 4;   // 16 -> M
    const int m0 = blockIdx.y * GBM;
    const int n0 = blockIdx.x * GBN;

    float acc[8][4];
#pragma unroll
    for (int i = 0; i < 8; i++)
#pragma unroll
        for (int j = 0; j < 4; j++) acc[i][j] = 0.0f;

    for (int k0 = 0; k0 < I_SZ; k0 += GBK) {
#pragma unroll
        for (int p = 0; p < 2; p++) {
            int q = tid + p * 256;
            int row = q >> 2, qc = q & 3;
            float4 v = *(const float4*)(X + (size_t)(m0 + row) * I_SZ + k0 + qc * 4);
            Xs[qc * 4 + 0][row] = v.x; Xs[qc * 4 + 1][row] = v.y;
            Xs[qc * 4 + 2][row] = v.z; Xs[qc * 4 + 3][row] = v.w;
        }
        {
            int row = tid >> 2, qc = tid & 3;
            float4 v = *(const float4*)(W + (size_t)(n0 + row) * I_SZ + k0 + qc * 4);
            Ws[qc * 4 + 0][row] = v.x; Ws[qc * 4 + 1][row] = v.y;
            Ws[qc * 4 + 2][row] = v.z; Ws[qc * 4 + 3][row] = v.w;
        }
        __syncthreads();
#pragma unroll
        for (int kk = 0; kk < GBK; kk++) {
            float a[8], bv[4];
            *(float4*)&a[0] = *(const float4*)&Xs[kk][ty * 8];
            *(float4*)&a[4] = *(const float4*)&Xs[kk][ty * 8 + 4];
            *(float4*)&bv[0] = *(const float4*)&Ws[kk][tx * 4];
#pragma unroll
            for (int i = 0; i < 8; i++)
#pragma unroll
                for (int j = 0; j < 4; j++)
                    acc[i][j] += a[i] * bv[j];
        }
        __syncthreads();
    }
#pragma unroll
    for (int i = 0; i < 8; i++) {
        float4 v = make_float4(acc[i][0], acc[i][1], acc[i][2], acc[i][3]);
        *(float4*)(C + (size_t)(m0 + ty * 8 + i) * H_SZ + n0 + tx * 4) = v;
    }
}

// ------------------------------------------------------------------
// Persistent recurrence kernel.
// grid = 128 blocks (64 j-tiles x 2 b-halves), 1024 threads.
// Block tile per step: 16 j x 16 b x 1024 k.
// Thread: (tb 0..3, tj 0..3, ks 0..63): 4x4 micro-tile over k-chunk of 16.
// U slab smem-resident for entire kernel; h staged per step via __ldcg.
// ------------------------------------------------------------------
#define JT 16
#define BHALF 16
#define KSPL 64
#define USTR (H_SZ + 4)
#define NOUT 256
#define RECUR_SMEM (((JT + BHALF) * USTR + NOUT * KSPL) * 4)

__global__ void __launch_bounds__(1024, 1) recur_kernel(
    float* __restrict__ states,      // [B, T, H] (holds xW on entry, states on exit)
    float* __restrict__ hfinal,      // [B, H]
    const float* __restrict__ U,     // [H, H]
    const float* __restrict__ bias,  // [H]
    const float* __restrict__ tau)   // [H]
{
    extern __shared__ float sm[];
    float* Us  = sm;                       // JT * USTR
    float* hs  = Us + JT * USTR;           // BHALF * USTR
    float* red = hs + BHALF * USTR;        // NOUT * KSPL (swizzled)

    const int tid = threadIdx.x;
    const int blk = blockIdx.x;
    const int jt = blk & 63;
    const int bh = blk >> 6;
    const int j0 = jt * JT;
    const int b0 = bh * BHALF;

    const int tb = tid & 3;
    const int tj = (tid >> 2) & 3;
    const int ks = tid >> 4;          // 0..63
    const int kbase = ks * 16;
    const int sbase = 2 * tb + 8 * tj;  // even; bit0 reserved for jj&1

    // Load U slab once: rows j0..j0+15, all k
    for (int q = tid; q < JT * (H_SZ / 4); q += 1024) {
        int row = q >> 8;
        int c = q & 255;
        float4 v = *(const float4*)(U + (size_t)(j0 + row) * H_SZ + c * 4);
        *(float4*)(Us + row * USTR + c * 4) = v;
    }

    // Epilogue thread mapping (tid < 256): permuted so stage-2 LDS is
    // conflict-free under the same swizzle the writers used.
    int op = 0, sred = 0, ej = 0, eb = 0, ebl = 0;
    float decay = 0.0f, biasj = 0.0f;
    if (tid < NOUT) {
        int tbp = tid & 3;
        int tjp = (tid >> 2) & 3;
        int jjl = (tid >> 4) & 1;
        int bbp = (tid >> 5) & 3;
        int jjh = (tid >> 7) & 1;
        int jjp = jjl | (jjh << 1);
        op = 64 * tjp + 16 * jjp + 4 * tbp + bbp;    // local output index
        sred = jjl | (2 * tbp) | (8 * tjp);          // swizzle key
        ej = j0 + (op >> 4);
        ebl = op & 15;
        eb = b0 + ebl;
        float it = 1.0f / tau[ej];
        decay = 1.0f - DT_C * it;
        biasj = bias[ej];
    }

    int cur = 0;
    __syncthreads();

    for (int t = 0; t < T_SZ; t++) {
        // Stage h half-slab from global double buffer (L1-bypass: data was
        // written by other SMs; L1 may be stale across barrier generations).
        for (int q = tid; q < BHALF * (H_SZ / 4); q += 1024) {
            int row = q >> 8;
            int c = q & 255;
            float4 v = __ldcg((const float4*)(g_h[cur] + (size_t)(b0 + row) * H_SZ + c * 4));
            *(float4*)(hs + row * USTR + c * 4) = v;
        }
        __syncthreads();

        // 4j x 4b micro-tile over this thread's 16-k chunk
        float acc[4][4];
#pragma unroll
        for (int jj = 0; jj < 4; jj++)
#pragma unroll
            for (int bb = 0; bb < 4; bb++) acc[jj][bb] = 0.0f;

#pragma unroll
        for (int kq = 0; kq < 4; kq++) {
            int k = kbase + kq * 4;
            float4 hv[4];
#pragma unroll
            for (int bb = 0; bb < 4; bb++)
                hv[bb] = *(const float4*)(hs + (tb * 4 + bb) * USTR + k);
#pragma unroll
            for (int jj = 0; jj < 4; jj++) {
                float4 uv = *(const float4*)(Us + (tj * 4 + jj) * USTR + k);
#pragma unroll
                for (int bb = 0; bb < 4; bb++) {
                    acc[jj][bb] += uv.x * hv[bb].x;
                    acc[jj][bb] += uv.y * hv[bb].y;
                    acc[jj][bb] += uv.z * hv[bb].z;
                    acc[jj][bb] += uv.w * hv[bb].w;
                }
            }
        }

        // Write partials with XOR-swizzled columns (conflict-free STS)
#pragma unroll
        for (int jj = 0; jj < 4; jj++)
#pragma unroll
            for (int bb = 0; bb < 4; bb++) {
                int oo = (tj * 4 + jj) * 16 + (tb * 4 + bb);
                int col = ks ^ (sbase | (jj & 1));
                red[oo * KSPL + col] = acc[jj][bb];
            }
        __syncthreads();

        if (tid < NOUT) {
            float sum = 0.0f;
#pragma unroll
            for (int i = 0; i < KSPL; i++)
                sum += red[op * KSPL + (i ^ sred)];
            float hold = hs[ebl * USTR + ej];       // h_old from the staged slab
            size_t sidx = ((size_t)eb * T_SZ + t) * H_SZ + ej;
            float xwv = __ldcg(states + sidx);
            float act = tanhf(xwv + sum + biasj);
            float hnew = decay * hold + DT_C * act;
            __stcg(states + sidx, hnew);
            __stcg(g_h[cur ^ 1] + (size_t)eb * H_SZ + ej, hnew);
            if (t == T_SZ - 1) __stcg(hfinal + (size_t)eb * H_SZ + ej, hnew);
            __threadfence();   // publish h_new device-wide before arrival
        }
        cur ^= 1;

        // -------- software grid barrier (all 128 blocks co-resident) -------
        __syncthreads();
        if (tid == 0) {
            g_arrive[blk] = t + 1;
        }
        if (blk == 0) {
            if (tid < RBLK) {
                while (g_arrive[tid] < t + 1) { }
            }
            __syncthreads();
            if (tid == 0) {
                __threadfence();
                g_release = t + 1;
            }
        }
        if (tid == 0) {
            while (g_release < t + 1) { }
            __threadfence();
        }
        __syncthreads();
    }
}

// ------------------------------------------------------------------
// Launcher
// ------------------------------------------------------------------
extern "C" void kernel_launch(void* const* d_in, const int* in_sizes, int n_in,
                              void* d_out, int out_size) {
    const float* x   = (const float*)d_in[0];   // [B, T, I]
    const float* W   = (const float*)d_in[1];   // [H, I]
    const float* U   = (const float*)d_in[2];   // [H, H]
    const float* b   = (const float*)d_in[3];   // [H]
    const float* tau = (const float*)d_in[4];   // [H]

    float* hfinal = (float*)d_out;              // [B, H]
    float* states = hfinal + B_SZ * H_SZ;       // [B, T, H]

    cudaFuncSetAttribute(recur_kernel,
                         cudaFuncAttributeMaxDynamicSharedMemorySize,
                         RECUR_SMEM);

    reset_kernel<<<32, 1024>>>();

    dim3 ggrid(H_SZ / GBN, (B_SZ * T_SZ) / GBM);
    gemm_xw<<<ggrid, 256>>>(x, W, states);

    recur_kernel<<<RBLK, 1024, RECUR_SMEM>>>(states, hfinal, U, b, tau);
}

// round 3
// speedup vs baseline: 1.3212x; 1.3212x over previous
#include <cuda_runtime.h>
#include <math.h>

#define B_SZ 32
#define T_SZ 1024
#define I_SZ 512
#define H_SZ 1024
#define DT_C 0.1f

typedef unsigned long long ull;

// ---------------- f32x2 packed-math helpers (Blackwell FFMA2) -------------
__device__ __forceinline__ ull ffma2(ull a, ull b, ull c) {
    ull d; asm("fma.rn.f32x2 %0, %1, %2, %3;" : "=l"(d) : "l"(a), "l"(b), "l"(c)); return d;
}
__device__ __forceinline__ ull fadd2(ull a, ull b) {
    ull d; asm("add.rn.f32x2 %0, %1, %2;" : "=l"(d) : "l"(a), "l"(b)); return d;
}
__device__ __forceinline__ ull pack2(float lo, float hi) {
    ull d; asm("mov.b64 %0, {%1, %2};" : "=l"(d) : "f"(lo), "f"(hi)); return d;
}
__device__ __forceinline__ float2 unpack2(ull v) {
    float2 r; asm("mov.b64 {%0, %1}, %2;" : "=f"(r.x), "=f"(r.y) : "l"(v)); return r;
}

// ------------------------------------------------------------------
// Persistent-kernel global state
// g_hT: transposed hidden state double buffer: [2][H][B]  (k-major)
// ------------------------------------------------------------------
#define RBLK 128
__device__ float g_hT[2][H_SZ * B_SZ];
__device__ volatile int g_arrive[RBLK];
__device__ volatile int g_release;

__global__ void reset_kernel() {
    int idx = blockIdx.x * blockDim.x + threadIdx.x;
    if (idx < H_SZ * B_SZ) g_hT[0][idx] = 0.0f;
    if (idx < RBLK) g_arrive[idx] = 0;
    if (idx == 0) g_release = 0;
}

// ------------------------------------------------------------------
// xW GEMM: C[M=B*T, H] = X[M, I] @ W[H, I]^T   (fp32, FFMA2 inner)
// 128x64 block tile, BK=16, 256 threads
// ------------------------------------------------------------------
#define GBM 128
#define GBN 64
#define GBK 16

union F4U { float4 f4; ull u[2]; };

__global__ void __launch_bounds__(256) gemm_xw(
    const float* __restrict__ X, const float* __restrict__ W,
    float* __restrict__ C)
{
    __shared__ float Xs[GBK][GBM];
    __shared__ float Ws[GBK][GBN + 4];
    const int tid = threadIdx.x;
    const int tx = tid & 15;   // 16 -> N
    const int ty = tid >> 4;   // 16 -> M
    const int m0 = blockIdx.y * GBM;
    const int n0 = blockIdx.x * GBN;

    ull acc2[4][4];   // [m-pair p][n j]
#pragma unroll
    for (int p = 0; p < 4; p++)
#pragma unroll
        for (int j = 0; j < 4; j++) acc2[p][j] = 0ull;

    for (int k0 = 0; k0 < I_SZ; k0 += GBK) {
#pragma unroll
        for (int pp = 0; pp < 2; pp++) {
            int q = tid + pp * 256;
            int row = q >> 2, qc = q & 3;
            float4 v = *(const float4*)(X + (size_t)(m0 + row) * I_SZ + k0 + qc * 4);
            Xs[qc * 4 + 0][row] = v.x; Xs[qc * 4 + 1][row] = v.y;
            Xs[qc * 4 + 2][row] = v.z; Xs[qc * 4 + 3][row] = v.w;
        }
        {
            int row = tid >> 2, qc = tid & 3;
            float4 v = *(const float4*)(W + (size_t)(n0 + row) * I_SZ + k0 + qc * 4);
            Ws[qc * 4 + 0][row] = v.x; Ws[qc * 4 + 1][row] = v.y;
            Ws[qc * 4 + 2][row] = v.z; Ws[qc * 4 + 3][row] = v.w;
        }
        __syncthreads();
#pragma unroll
        for (int kk = 0; kk < GBK; kk++) {
            F4U a0, a1;
            a0.f4 = *(const float4*)&Xs[kk][ty * 8];
            a1.f4 = *(const float4*)&Xs[kk][ty * 8 + 4];
            float4 bv = *(const float4*)&Ws[kk][tx * 4];
            ull bd[4];
            bd[0] = pack2(bv.x, bv.x); bd[1] = pack2(bv.y, bv.y);
            bd[2] = pack2(bv.z, bv.z); bd[3] = pack2(bv.w, bv.w);
            ull a2[4] = {a0.u[0], a0.u[1], a1.u[0], a1.u[1]};
#pragma unroll
            for (int p = 0; p < 4; p++)
#pragma unroll
                for (int j = 0; j < 4; j++)
                    acc2[p][j] = ffma2(a2[p], bd[j], acc2[p][j]);
        }
        __syncthreads();
    }
#pragma unroll
    for (int p = 0; p < 4; p++) {
        float2 c0 = unpack2(acc2[p][0]);
        float2 c1 = unpack2(acc2[p][1]);
        float2 c2 = unpack2(acc2[p][2]);
        float2 c3 = unpack2(acc2[p][3]);
        float4 lo = make_float4(c0.x, c1.x, c2.x, c3.x);
        float4 hi = make_float4(c0.y, c1.y, c2.y, c3.y);
        *(float4*)(C + (size_t)(m0 + ty * 8 + 2 * p)     * H_SZ + n0 + tx * 4) = lo;
        *(float4*)(C + (size_t)(m0 + ty * 8 + 2 * p + 1) * H_SZ + n0 + tx * 4) = hi;
    }
}

// ------------------------------------------------------------------
// Persistent recurrence kernel.
// grid = 128 blocks (64 j-tiles x 2 b-halves), 512 threads.
// Block tile per step: 16 j x 16 b x 1024 k.
// Thread (tb=tid&1, tj=(tid>>1)&3, ks=tid>>3): 4j x 4 b-pairs x 16k.
//   b-pair owned by (m, tb): pair index p = 2m + tb (floats 4m+2tb, +1).
// U in SMEM, stride 1025 (conflict-free scalar LDS).
// h staged k-major: hs[k][16 b], stride 20 (conflict-free LDS.64).
// ------------------------------------------------------------------
#define JT 16
#define BHALF 16
#define USTR 1025
#define HSTR 20
#define NPO 128
#define RECUR_SMEM ((JT * USTR + H_SZ * HSTR) * 4 + NPO * 64 * 8)

__global__ void __launch_bounds__(512, 1) recur_kernel(
    float* __restrict__ states,      // [B, T, H] (holds xW on entry, states on exit)
    float* __restrict__ hfinal,      // [B, H]
    const float* __restrict__ U,     // [H, H]
    const float* __restrict__ bias,  // [H]
    const float* __restrict__ tau)   // [H]
{
    extern __shared__ float sm[];
    float* Us = sm;                                 // [JT][USTR]
    float* hs = Us + JT * USTR;                     // [1024][HSTR]
    ull* red = (ull*)(hs + H_SZ * HSTR);            // [NPO][64]

    const int tid = threadIdx.x;
    const int blk = blockIdx.x;
    const int jt = blk & 63;
    const int bh = blk >> 6;
    const int j0 = jt * JT;
    const int bg0 = bh * BHALF;

    const int tb = tid & 1;
    const int tj = (tid >> 1) & 3;
    const int ks = tid >> 3;      // 0..63

    // ---- load U slab into smem: Us[row][k], row = 0..15 ----
    for (int q = tid; q < JT * (H_SZ / 4); q += 512) {
        int row = q >> 8;
        int c = (q & 255) * 4;
        float4 v = *(const float4*)(U + (size_t)(j0 + row) * H_SZ + c);
        float* d = Us + row * USTR + c;
        d[0] = v.x; d[1] = v.y; d[2] = v.z; d[3] = v.w;
    }

    // ---- epilogue (reader) setup: tid < 128, sr = tid & 15 ----
    int po = 0, sr = 0, jg = 0, bp = 0;
    float decay = 0.0f, biasj = 0.0f;
    size_t sidx0 = 0, sidx1 = 0;
    float xwA = 0.0f, xwB = 0.0f;
    if (tid < NPO) {
        int r = tid;
        // po bits: 0<-r1, 1<-r0, 2<-r4, 3<-r5, 4<-r6, 5<-r2, 6<-r3 (bijection)
        po = ((r >> 1) & 1) | ((r & 1) << 1) | (((r >> 4) & 1) << 2)
           | (((r >> 5) & 1) << 3) | (((r >> 6) & 1) << 4)
           | (((r >> 2) & 1) << 5) | (((r >> 3) & 1) << 6);
        sr = r & 15;   // equals writer constant f(po) by construction
        int j_loc = po >> 3;
        bp = po & 7;
        jg = j0 + j_loc;
        float it = 1.0f / tau[jg];
        decay = 1.0f - DT_C * it;
        biasj = bias[jg];
        int b_glob = bg0 + 2 * bp;
        sidx0 = (size_t)b_glob * T_SZ * H_SZ + jg;
        sidx1 = sidx0 + (size_t)T_SZ * H_SZ;
        xwA = __ldcg(states + sidx0);   // prefetch t = 0
        xwB = __ldcg(states + sidx1);
    }

    int cur = 0;
    __syncthreads();

    for (int t = 0; t < T_SZ; t++) {
        // ---- stage h^T half-slab: hs[k][0..15] <- g_hT[cur][k][bg0..+15] ----
        const float* gh = g_hT[cur] + bg0;
#pragma unroll
        for (int it8 = 0; it8 < 8; it8++) {
            int q = tid + it8 * 512;
            int k = q >> 2, part = (q & 3) * 4;
            float4 v = __ldcg((const float4*)(gh + (size_t)k * B_SZ + part));
            float* d = hs + k * HSTR + part;
            d[0] = v.x; d[1] = v.y; d[2] = v.z; d[3] = v.w;
        }
        __syncthreads();

        // ---- compute: acc2[jj][m] over k = ks + 64*kq ----
        ull acc2[4][4];
#pragma unroll
        for (int jj = 0; jj < 4; jj++)
#pragma unroll
            for (int m = 0; m < 4; m++) acc2[jj][m] = 0ull;

        const float* urow = Us + tj * 4 * USTR + ks;
#pragma unroll
        for (int kq = 0; kq < 16; kq++) {
            int k = ks + 64 * kq;
            const float* hrow = hs + k * HSTR + 2 * tb;
            ull h0 = *(const ull*)(hrow + 0);
            ull h1 = *(const ull*)(hrow + 4);
            ull h2 = *(const ull*)(hrow + 8);
            ull h3 = *(const ull*)(hrow + 12);
#pragma unroll
            for (int jj = 0; jj < 4; jj++) {
                float us = urow[jj * USTR + 64 * kq];
                ull ud = pack2(us, us);
                acc2[jj][0] = ffma2(ud, h0, acc2[jj][0]);
                acc2[jj][1] = ffma2(ud, h1, acc2[jj][1]);
                acc2[jj][2] = ffma2(ud, h2, acc2[jj][2]);
                acc2[jj][3] = ffma2(ud, h3, acc2[jj][3]);
            }
        }

        // ---- write partials, XOR-swizzled (2-phase-optimal STS.64) ----
#pragma unroll
        for (int jj = 0; jj < 4; jj++)
#pragma unroll
            for (int m = 0; m < 4; m++) {
                int p = (tj * 4 + jj) * 8 + 2 * m + tb;
                int col = ks ^ ((m & 1) | (tb << 1) | (tj << 2));
                red[p * 64 + col] = acc2[jj][m];
            }
        __syncthreads();

        // ---- reduce + pointwise epilogue (128 readers) ----
        if (tid < NPO) {
            ull s01 = 0ull, s23 = 0ull;
#pragma unroll
            for (int i = 0; i < 64; i += 2) {
                s01 = fadd2(s01, red[po * 64 + (i ^ sr)]);
                s23 = fadd2(s23, red[po * 64 + ((i + 1) ^ sr)]);
            }
            float2 sum = unpack2(fadd2(s01, s23));
            float2 hold = *(const float2*)(hs + jg * HSTR + 2 * bp);
            float a0 = tanhf(xwA + sum.x + biasj);
            float a1 = tanhf(xwB + sum.y + biasj);
            float h0n = decay * hold.x + DT_C * a0;
            float h1n = decay * hold.y + DT_C * a1;
            size_t off = (size_t)t * H_SZ;
            __stcg(states + sidx0 + off, h0n);
            __stcg(states + sidx1 + off, h1n);
            float2 hn = make_float2(h0n, h1n);
            __stcg((float2*)(g_hT[cur ^ 1] + (size_t)jg * B_SZ + bg0 + 2 * bp), hn);
            if (t == T_SZ - 1) {
                __stcg(hfinal + (size_t)(bg0 + 2 * bp) * H_SZ + jg, h0n);
                __stcg(hfinal + (size_t)(bg0 + 2 * bp + 1) * H_SZ + jg, h1n);
            } else {
                xwA = __ldcg(states + sidx0 + off + H_SZ);   // prefetch t+1
                xwB = __ldcg(states + sidx1 + off + H_SZ);
            }
        }
        cur ^= 1;

        // -------- software grid barrier (R1-proven two-hop topology) -------
        __syncthreads();
        if (tid == 0) {
            __threadfence();
            g_arrive[blk] = t + 1;
        }
        if (blk == 0) {
            if (tid < RBLK) {
                while (g_arrive[tid] < t + 1) { }
            }
            __syncthreads();
            if (tid == 0) {
                __threadfence();
                g_release = t + 1;
            }
        }
        if (tid == 0) {
            while (g_release < t + 1) { }
            __threadfence();
        }
        __syncthreads();
    }
}

// ------------------------------------------------------------------
// Launcher
// ------------------------------------------------------------------
extern "C" void kernel_launch(void* const* d_in, const int* in_sizes, int n_in,
                              void* d_out, int out_size) {
    const float* x   = (const float*)d_in[0];   // [B, T, I]
    const float* W   = (const float*)d_in[1];   // [H, I]
    const float* U   = (const float*)d_in[2];   // [H, H]
    const float* b   = (const float*)d_in[3];   // [H]
    const float* tau = (const float*)d_in[4];   // [H]

    float* hfinal = (float*)d_out;              // [B, H]
    float* states = hfinal + B_SZ * H_SZ;       // [B, T, H]

    cudaFuncSetAttribute(recur_kernel,
                         cudaFuncAttributeMaxDynamicSharedMemorySize,
                         RECUR_SMEM);

    reset_kernel<<<32, 1024>>>();

    dim3 ggrid(H_SZ / GBN, (B_SZ * T_SZ) / GBM);
    gemm_xw<<<ggrid, 256>>>(x, W, states);

    recur_kernel<<<RBLK, 512, RECUR_SMEM>>>(states, hfinal, U, b, tau);
}